// round 5
// baseline (speedup 1.0000x reference)
#include <cuda_runtime.h>
#include <cuda_fp16.h>
#include <math.h>

#define BB 32
#define NN 16384
#define DD 64
#define SS 7
#define HH 128
#define TILE 256
#define TPB 256
#define TILES_PER_B (NN / TILE)   // 64

__device__ __align__(16) float g_P[DD*DD];
__device__ __align__(16) float g_slots[BB*SS*DD];
__device__ __align__(16) float g_h0[BB*DD];
__device__ __align__(16) float g_qp[BB*SS*DD];
__device__ __align__(16) float g_U[BB*SS*DD];
__device__ float g_Z[BB*SS];
__device__ __align__(16) float g_gi[BB*SS*3*DD];        // GRU input gates
__device__ __align__(16) __half g_xn[(long)BB*NN*DD];   // 64 MB LN(x) cache

// ---- k_attn smem layout (floats) ----
#define OFF_XN   0        // 256 rows * 9 f4 = 9216 fl (fp16 data)
#define OFF_PT   9216     // 256*8 probs fp32
#define OFF_QP   11264    // 112 f4 = 448 fl
#define ATTN_SMEM_BYTES ((11712)*4)

// ---- k_prep smem layout (floats) ----
#define P_IN  0           // 128 rows * 17 f4 = 8704 fl
#define P_OUT 8704        // 128 rows * 9 f4  = 4608 fl
#define P_G   13312
#define P_B   13376
#define PREP_SMEM_BYTES ((13440)*4)

// ---- k_upd2 smem layout (floats) ----
#define V_WHH 0           // 192*68 = 13056
#define V_W1  13056       // 128*68 = 8704
#define V_W2  21760       // 64*132 = 8448
#define V_GI  30208       // 1344
#define V_SL  31552       // 448
#define V_XB  32000       // 448
#define V_HID 32448       // 896
#define V_H   33344       // 64
#define V_GH  33408       // 192
#define V_M7  33600       // 8
#define V_R7  33608       // 8
#define UPD2_SMEM_BYTES ((33616)*4)

__device__ __forceinline__ void h8_to_f(const uint4& v, float* f) {
    const __half2* h = (const __half2*)&v;
    float2 t;
    t = __half22float2(h[0]); f[0]=t.x; f[1]=t.y;
    t = __half22float2(h[1]); f[2]=t.x; f[3]=t.y;
    t = __half22float2(h[2]); f[4]=t.x; f[5]=t.y;
    t = __half22float2(h[3]); f[6]=t.x; f[7]=t.y;
}
__device__ __forceinline__ void h4_to_f(const uint2& v, float* f) {
    const __half2* h = (const __half2*)&v;
    float2 t;
    t = __half22float2(h[0]); f[0]=t.x; f[1]=t.y;
    t = __half22float2(h[1]); f[2]=t.x; f[3]=t.y;
}
__device__ __forceinline__ unsigned pack_h2(float a, float b) {
    __half2 h = __float22half2_rn(make_float2(a, b));
    return *(unsigned*)&h;
}

// ---------------------------------------------------------------------------
// k_setup: blocks 0..31 -> slots/h0 init + zero U,Z.  block 32 -> P = Wq^T Wk
// ---------------------------------------------------------------------------
__global__ void k_setup(const float* __restrict__ mu, const float* __restrict__ lsig,
                        const float* __restrict__ nslots, const float* __restrict__ nh,
                        const float* __restrict__ Wq, const float* __restrict__ Wk) {
    int blk = blockIdx.x, tid = threadIdx.x;
    if (blk < BB) {
        int b = blk;
        for (int i = tid; i < SS*DD; i += blockDim.x) {
            int d = i & (DD-1);
            float sg = __expf(lsig[d]);
            g_slots[b*SS*DD + i] = mu[d] + sg * nslots[b*SS*DD + i];
            g_U[b*SS*DD + i] = 0.f;
        }
        for (int d = tid; d < DD; d += blockDim.x) {
            float sg = __expf(lsig[d]);
            g_h0[b*DD + d] = mu[d] + sg * nh[b*DD + d];
        }
        if (tid < SS) g_Z[b*SS + tid] = 0.f;
    } else {
        __shared__ float sq[DD*DD], sk[DD*DD];
        for (int i = tid; i < DD*DD; i += blockDim.x) { sq[i] = Wq[i]; sk[i] = Wk[i]; }
        __syncthreads();
        for (int i = tid; i < DD*DD; i += blockDim.x) {
            int dp = i >> 6, d = i & 63;
            float acc = 0.f;
            for (int e = 0; e < DD; e++) acc += sq[e*DD+dp] * sk[e*DD+d];
            g_P[i] = acc;
        }
    }
}

// ---------------------------------------------------------------------------
// k_prep: LN(inputs) -> g_xn (fp16), coalesced in & out via smem bounce
// ---------------------------------------------------------------------------
__global__ __launch_bounds__(256)
void k_prep(const float* __restrict__ x_in,
            const float* __restrict__ lg, const float* __restrict__ lb) {
    extern __shared__ __align__(16) float sp[];
    float4* s_in  = (float4*)(sp + P_IN);      // [128][17]
    uint4*  s_out = (uint4*)(sp + P_OUT);      // [128][9]
    float*  s_g   = sp + P_G;
    float*  s_b   = sp + P_B;
    int tid = threadIdx.x;
    long row_base = (long)blockIdx.x * 128;

    if (tid < DD) { s_g[tid] = lg[tid]; s_b[tid] = lb[tid]; }
    const float4* gin = (const float4*)x_in + row_base*16;
#pragma unroll
    for (int jj = 0; jj < 8; jj++) {
        int li = jj*256 + tid;
        s_in[(li>>4)*17 + (li&15)] = gin[li];
    }
    __syncthreads();

    if (tid < 128) {
        const float4* xr = s_in + tid*17;
        float4 x[16];
#pragma unroll
        for (int j = 0; j < 16; j++) x[j] = xr[j];
        float sm = 0.f, sq = 0.f;
#pragma unroll
        for (int j = 0; j < 16; j++) {
            sm += x[j].x + x[j].y + x[j].z + x[j].w;
            sq += x[j].x*x[j].x + x[j].y*x[j].y + x[j].z*x[j].z + x[j].w*x[j].w;
        }
        float m = sm * (1.f/DD);
        float rstd = rsqrtf(sq*(1.f/DD) - m*m + 1e-5f);
#pragma unroll
        for (int j = 0; j < 8; j++) {
            float4 a = x[2*j], c = x[2*j+1];
            float n0 = (a.x-m)*rstd*s_g[8*j+0] + s_b[8*j+0];
            float n1 = (a.y-m)*rstd*s_g[8*j+1] + s_b[8*j+1];
            float n2 = (a.z-m)*rstd*s_g[8*j+2] + s_b[8*j+2];
            float n3 = (a.w-m)*rstd*s_g[8*j+3] + s_b[8*j+3];
            float n4 = (c.x-m)*rstd*s_g[8*j+4] + s_b[8*j+4];
            float n5 = (c.y-m)*rstd*s_g[8*j+5] + s_b[8*j+5];
            float n6 = (c.z-m)*rstd*s_g[8*j+6] + s_b[8*j+6];
            float n7 = (c.w-m)*rstd*s_g[8*j+7] + s_b[8*j+7];
            uint4 o;
            o.x = pack_h2(n0, n1);
            o.y = pack_h2(n2, n3);
            o.z = pack_h2(n4, n5);
            o.w = pack_h2(n6, n7);
            s_out[tid*9 + j] = o;
        }
    }
    __syncthreads();

    uint4* gout = (uint4*)g_xn + row_base*8;
#pragma unroll
    for (int jj = 0; jj < 4; jj++) {
        int li = jj*256 + tid;
        gout[li] = s_out[(li>>3)*9 + (li&7)];
    }
}

// ---------------------------------------------------------------------------
// k_qp0: q'[b,s,:] = scale * LN_slots(slots[b,s]) @ P
// ---------------------------------------------------------------------------
__global__ void k_qp0(const float* __restrict__ lsg, const float* __restrict__ lsb) {
    int b = blockIdx.x, tid = threadIdx.x;
    __shared__ float sl[SS*DD], sn[SS*DD], m7[SS], r7[SS];
    for (int i = tid; i < SS*DD; i += blockDim.x) sl[i] = g_slots[b*SS*DD+i];
    __syncthreads();
    if (tid < SS) {
        float sm = 0.f, sq = 0.f;
        for (int d = 0; d < DD; d++) { float v = sl[tid*DD+d]; sm += v; sq += v*v; }
        float m = sm * (1.f/DD);
        m7[tid] = m;
        r7[tid] = rsqrtf(sq*(1.f/DD) - m*m + 1e-5f);
    }
    __syncthreads();
    for (int i = tid; i < SS*DD; i += blockDim.x) {
        int s = i >> 6, d = i & 63;
        sn[i] = (sl[i]-m7[s])*r7[s]*lsg[d] + lsb[d];
    }
    __syncthreads();
    for (int o = tid; o < SS*DD; o += blockDim.x) {
        int s = o >> 6, d = o & 63;
        float acc = 0.f;
        for (int dp = 0; dp < DD; dp++) acc += sn[s*DD+dp] * g_P[dp*DD+d];
        g_qp[b*SS*DD+o] = 0.125f * acc;
    }
}

// ---------------------------------------------------------------------------
// k_attn: logits -> softmax -> outer-product with direct global reduction
// ---------------------------------------------------------------------------
__global__ __launch_bounds__(TPB, 4)
void k_attn() {
    extern __shared__ __align__(16) float smem[];
    uint4*  s_xn4 = (uint4*)(smem + OFF_XN);     // [256][9] fp16 rows
    float*  s_pT  = smem + OFF_PT;               // [256][8] probs fp32
    float4* s_qp4 = (float4*)(smem + OFF_QP);    // [7][16]

    int b   = blockIdx.x >> 6;
    int rb  = (blockIdx.x & (TILES_PER_B-1)) * TILE;
    int tid = threadIdx.x;

    // phase 0: coalesced tile copy + q' load
    {
        const uint4* gx = (const uint4*)g_xn + ((long)b*NN + rb)*8;
#pragma unroll
        for (int jj = 0; jj < 8; jj++) {
            int li = jj*256 + tid;
            s_xn4[(li>>3)*9 + (li&7)] = gx[li];
        }
        for (int i = tid; i < SS*DD/4; i += TPB)
            s_qp4[i] = ((const float4*)(g_qp + b*SS*DD))[i];
    }
    __syncthreads();

    // phase 1: one row per thread -> logits -> softmax -> probs (fp32)
    {
        const uint4* xr = s_xn4 + tid*9;
        float acc[SS];
#pragma unroll
        for (int s = 0; s < SS; s++) acc[s] = 0.f;
#pragma unroll
        for (int j = 0; j < 8; j++) {
            uint4 xv = xr[j];
            float xf[8]; h8_to_f(xv, xf);
#pragma unroll
            for (int s = 0; s < SS; s++) {
                float4 qa = s_qp4[s*16 + 2*j];
                float4 qb = s_qp4[s*16 + 2*j + 1];
                acc[s] += xf[0]*qa.x + xf[1]*qa.y + xf[2]*qa.z + xf[3]*qa.w
                        + xf[4]*qb.x + xf[5]*qb.y + xf[6]*qb.z + xf[7]*qb.w;
            }
        }
        float mx = acc[0];
#pragma unroll
        for (int s = 1; s < SS; s++) mx = fmaxf(mx, acc[s]);
        float es[SS], se = 0.f;
#pragma unroll
        for (int s = 0; s < SS; s++) { es[s] = __expf(acc[s]-mx); se += es[s]; }
        float inv = 1.f/se;
        float4* pr = (float4*)(s_pT + tid*8);
        pr[0] = make_float4(es[0]*inv+1e-8f, es[1]*inv+1e-8f,
                            es[2]*inv+1e-8f, es[3]*inv+1e-8f);
        pr[1] = make_float4(es[4]*inv+1e-8f, es[5]*inv+1e-8f,
                            es[6]*inv+1e-8f, 0.f);
    }
    __syncthreads();

    // phase 2: (g 0..15, hc 0..15): 16 rows x 4 halves each; fp32 accumulate;
    // pairwise shuffle merge (g, g^1 within warp), then direct global REDs.
    {
        int g = tid >> 4, hc = tid & 15;
        float a[SS][4];
#pragma unroll
        for (int s = 0; s < SS; s++)
#pragma unroll
            for (int k = 0; k < 4; k++) a[s][k] = 0.f;
        float z[SS];
#pragma unroll
        for (int s = 0; s < SS; s++) z[s] = 0.f;

        const uint2* x2 = (const uint2*)(smem + OFF_XN);
        int r0 = g*16;
#pragma unroll 4
        for (int rr = 0; rr < 16; rr++) {
            int r = r0 + rr;
            uint2 xv = x2[r*18 + hc];            // row pitch 9 f4 = 18 uint2
            float xf[4]; h4_to_f(xv, xf);
            float4 pA = *(const float4*)(s_pT + r*8);
            float4 pB = *(const float4*)(s_pT + r*8 + 4);
            float p[SS] = {pA.x, pA.y, pA.z, pA.w, pB.x, pB.y, pB.z};
#pragma unroll
            for (int s = 0; s < SS; s++) {
#pragma unroll
                for (int k = 0; k < 4; k++) a[s][k] += p[s]*xf[k];
            }
            if (hc == 0) {
#pragma unroll
                for (int s = 0; s < SS; s++) z[s] += p[s];
            }
        }
#pragma unroll
        for (int s = 0; s < SS; s++) {
#pragma unroll
            for (int k = 0; k < 4; k++)
                a[s][k] += __shfl_xor_sync(0xffffffffu, a[s][k], 16);
        }
        if ((tid & 16) == 0) {
            float* ub = g_U + b*SS*DD;
#pragma unroll
            for (int s = 0; s < SS; s++) {
#pragma unroll
                for (int k = 0; k < 4; k++)
                    atomicAdd(&ub[s*DD + hc*4 + k], a[s][k]);
            }
        }
#pragma unroll
        for (int s = 0; s < SS; s++)
            z[s] += __shfl_xor_sync(0xffffffffu, z[s], 16);
        if ((tid & 31) == 0) {
#pragma unroll
            for (int s = 0; s < SS; s++)
                atomicAdd(&g_Z[b*SS+s], z[s]);
        }
    }
}

// ---------------------------------------------------------------------------
// k_upd1: per (b,s): updates = (U . Wv^T)/Z, then gi = upd @ w_ih^T + b_ih
// ---------------------------------------------------------------------------
__global__ __launch_bounds__(192)
void k_upd1(const float* __restrict__ Wv,
            const float* __restrict__ w_ih, const float* __restrict__ b_ih) {
    int blk = blockIdx.x;           // 0..223
    int b = blk / SS, s = blk - b*SS;
    int tid = threadIdx.x;
    __shared__ float sU[DD], supd[DD];
    __shared__ float sZ;

    if (tid < DD) sU[tid] = g_U[(b*SS+s)*DD + tid];
    if (tid == 0) sZ = g_Z[b*SS+s];
    __syncthreads();

    if (tid < DD) {
        const float4* w = (const float4*)(Wv + tid*DD);
        const float4* u = (const float4*)sU;
        float a0=0,a1=0,a2=0,a3=0;
#pragma unroll
        for (int j = 0; j < 16; j++) {
            float4 a = u[j], c = w[j];
            a0 += a.x*c.x; a1 += a.y*c.y; a2 += a.z*c.z; a3 += a.w*c.w;
        }
        supd[tid] = ((a0+a1)+(a2+a3)) / sZ;
    }
    __syncthreads();

    {
        const float4* w = (const float4*)(w_ih + tid*DD);
        const float4* u = (const float4*)supd;
        float a0=b_ih[tid],a1=0,a2=0,a3=0;
#pragma unroll
        for (int j = 0; j < 16; j++) {
            float4 a = u[j], c = w[j];
            a0 += a.x*c.x; a1 += a.y*c.y; a2 += a.z*c.z; a3 += a.w*c.w;
        }
        g_gi[(b*SS+s)*3*DD + tid] = (a0+a1)+(a2+a3);
    }
}

// ---------------------------------------------------------------------------
// k_upd2: GRU over slots (smem-staged weights) -> MLP -> slots + next q'
// ---------------------------------------------------------------------------
__global__ __launch_bounds__(256)
void k_upd2(const float* __restrict__ w_hh, const float* __restrict__ b_hh,
            const float* __restrict__ w1, const float* __restrict__ b1,
            const float* __restrict__ w2, const float* __restrict__ b2,
            const float* __restrict__ lsg, const float* __restrict__ lsb,
            const float* __restrict__ lmg, const float* __restrict__ lmb,
            float* __restrict__ dout, int last) {
    extern __shared__ __align__(16) float sm[];
    float* whh = sm + V_WHH;     // [192][68]
    float* w1s = sm + V_W1;      // [128][68]
    float* w2s = sm + V_W2;      // [64][132]
    float* gis = sm + V_GI;      // [7][192]
    float* sl  = sm + V_SL;      // [7][64]
    float* xb  = sm + V_XB;
    float* hid = sm + V_HID;     // [7][128]
    float* h   = sm + V_H;
    float* ghs = sm + V_GH;      // [192]
    float* m7  = sm + V_M7;
    float* r7  = sm + V_R7;

    int b = blockIdx.x, tid = threadIdx.x;

    for (int i = tid; i < 3*DD*DD; i += 256) { int r = i>>6, e = i&63; whh[r*68+e] = w_hh[i]; }
    for (int i = tid; i < HH*DD;   i += 256) { int r = i>>6, e = i&63; w1s[r*68+e] = w1[i]; }
    for (int i = tid; i < DD*HH;   i += 256) { int r = i>>7, k = i&127; w2s[r*132+k] = w2[i]; }
    for (int i = tid; i < SS*3*DD; i += 256) gis[i] = g_gi[b*SS*3*DD + i];
    if (tid < DD) h[tid] = g_h0[b*DD+tid];
    __syncthreads();

    // GRU over slot axis
    for (int s = 0; s < SS; s++) {
        if (tid < 3*DD) {
            const float4* w = (const float4*)(whh + tid*68);
            const float4* hv = (const float4*)h;
            float a0=b_hh[tid],a1=0,a2=0,a3=0;
#pragma unroll
            for (int j = 0; j < 16; j++) {
                float4 c = w[j], a = hv[j];
                a0 += a.x*c.x; a1 += a.y*c.y; a2 += a.z*c.z; a3 += a.w*c.w;
            }
            ghs[tid] = (a0+a1)+(a2+a3);
        }
        __syncthreads();
        if (tid < DD) {
            float r = 1.f/(1.f + __expf(-(gis[s*192+tid]     + ghs[tid])));
            float z = 1.f/(1.f + __expf(-(gis[s*192+64+tid]  + ghs[64+tid])));
            float nx = gis[s*192+128+tid] + r*ghs[128+tid];
            float n = 1.f - 2.f/(__expf(2.f*nx) + 1.f);   // tanh
            float hn = (1.f-z)*n + z*h[tid];
            h[tid] = hn;
            sl[s*DD+tid] = hn;
        }
        __syncthreads();
    }

    // MLP: slots += relu(LN_mlp(slots) @ w1^T + b1) @ w2^T + b2
    if (tid < SS) {
        float smv = 0.f, sq = 0.f;
        for (int d = 0; d < DD; d++) { float v = sl[tid*DD+d]; smv += v; sq += v*v; }
        float m = smv*(1.f/DD);
        m7[tid] = m; r7[tid] = rsqrtf(sq*(1.f/DD) - m*m + 1e-5f);
    }
    __syncthreads();
    for (int i = tid; i < SS*DD; i += 256) {
        int s = i >> 6, d = i & 63;
        xb[i] = (sl[i]-m7[s])*r7[s]*lmg[d] + lmb[d];
    }
    __syncthreads();
    for (int o = tid; o < SS*HH; o += 256) {
        int s = o >> 7, hc = o & 127;
        const float4* w = (const float4*)(w1s + hc*68);
        const float4* u = (const float4*)(xb + s*DD);
        float a0=b1[hc],a1=0,a2=0,a3=0;
#pragma unroll
        for (int j = 0; j < 16; j++) {
            float4 a = u[j], c = w[j];
            a0 += a.x*c.x; a1 += a.y*c.y; a2 += a.z*c.z; a3 += a.w*c.w;
        }
        hid[o] = fmaxf((a0+a1)+(a2+a3), 0.f);
    }
    __syncthreads();
    for (int o = tid; o < SS*DD; o += 256) {
        int s = o >> 6, d = o & 63;
        const float4* w = (const float4*)(w2s + d*132);
        const float4* u = (const float4*)(hid + s*HH);
        float a0=b2[d],a1=0,a2=0,a3=0;
#pragma unroll
        for (int j = 0; j < 32; j++) {
            float4 a = u[j], c = w[j];
            a0 += a.x*c.x; a1 += a.y*c.y; a2 += a.z*c.z; a3 += a.w*c.w;
        }
        float v = sl[o] + (a0+a1)+(a2+a3);
        sl[o] = v;                     // new slots
        g_slots[b*SS*DD+o] = v;
        dout[b*SS*DD+o] = v;
    }
    __syncthreads();

    if (!last) {
        if (tid < SS) {
            float smv = 0.f, sq = 0.f;
            for (int d = 0; d < DD; d++) { float v = sl[tid*DD+d]; smv += v; sq += v*v; }
            float m = smv*(1.f/DD);
            m7[tid] = m; r7[tid] = rsqrtf(sq*(1.f/DD) - m*m + 1e-5f);
        }
        __syncthreads();
        for (int i = tid; i < SS*DD; i += 256) {
            int s = i >> 6, d = i & 63;
            xb[i] = (sl[i]-m7[s])*r7[s]*lsg[d] + lsb[d];
        }
        __syncthreads();
        for (int o = tid; o < SS*DD; o += 256) {
            int s = o >> 6, d = o & 63;
            float a0=0,a1=0,a2=0,a3=0;
#pragma unroll
            for (int dp = 0; dp < DD; dp += 4) {
                a0 += xb[s*DD+dp+0]*g_P[(dp+0)*DD+d];
                a1 += xb[s*DD+dp+1]*g_P[(dp+1)*DD+d];
                a2 += xb[s*DD+dp+2]*g_P[(dp+2)*DD+d];
                a3 += xb[s*DD+dp+3]*g_P[(dp+3)*DD+d];
            }
            g_qp[b*SS*DD+o] = 0.125f*((a0+a1)+(a2+a3));
            g_U[b*SS*DD+o] = 0.f;
        }
        if (tid < SS) g_Z[b*SS+tid] = 0.f;
    }
}

// ---------------------------------------------------------------------------
extern "C" void kernel_launch(void* const* d_in, const int* in_sizes, int n_in,
                              void* d_out, int out_size) {
    const float* inputs     = (const float*)d_in[0];
    const float* ln_in_g    = (const float*)d_in[1];
    const float* ln_in_b    = (const float*)d_in[2];
    const float* ln_slots_g = (const float*)d_in[3];
    const float* ln_slots_b = (const float*)d_in[4];
    const float* ln_mlp_g   = (const float*)d_in[5];
    const float* ln_mlp_b   = (const float*)d_in[6];
    const float* Wq         = (const float*)d_in[7];
    const float* Wk         = (const float*)d_in[8];
    const float* Wv         = (const float*)d_in[9];
    const float* mu         = (const float*)d_in[10];
    const float* lsig       = (const float*)d_in[11];
    const float* w_ih       = (const float*)d_in[12];
    const float* w_hh       = (const float*)d_in[13];
    const float* b_ih       = (const float*)d_in[14];
    const float* b_hh       = (const float*)d_in[15];
    const float* w1         = (const float*)d_in[16];
    const float* b1         = (const float*)d_in[17];
    const float* w2         = (const float*)d_in[18];
    const float* b2         = (const float*)d_in[19];
    const float* nslots     = (const float*)d_in[20];
    const float* nh         = (const float*)d_in[21];
    float* out = (float*)d_out;

    cudaFuncSetAttribute(k_prep,  cudaFuncAttributeMaxDynamicSharedMemorySize, PREP_SMEM_BYTES);
    cudaFuncSetAttribute(k_attn,  cudaFuncAttributeMaxDynamicSharedMemorySize, ATTN_SMEM_BYTES);
    cudaFuncSetAttribute(k_upd2,  cudaFuncAttributeMaxDynamicSharedMemorySize, UPD2_SMEM_BYTES);

    k_setup<<<BB+1, 256>>>(mu, lsig, nslots, nh, Wq, Wk);
    k_prep<<<(BB*NN)/128, 256, PREP_SMEM_BYTES>>>(inputs, ln_in_g, ln_in_b);
    k_qp0<<<BB, 256>>>(ln_slots_g, ln_slots_b);
    for (int it = 0; it < 3; it++) {
        k_attn<<<BB*TILES_PER_B, TPB, ATTN_SMEM_BYTES>>>();
        k_upd1<<<BB*SS, 192>>>(Wv, w_ih, b_ih);
        k_upd2<<<BB, 256, UPD2_SMEM_BYTES>>>(w_hh, b_hh, w1, b1, w2, b2,
                                             ln_slots_g, ln_slots_b, ln_mlp_g, ln_mlp_b,
                                             out, it == 2);
    }
}

// round 6
// speedup vs baseline: 1.5700x; 1.5700x over previous
#include <cuda_runtime.h>
#include <cuda_fp16.h>
#include <math.h>

#define BB 32
#define NN 16384
#define DD 64
#define SS 7
#define HH 128
#define TILE 256
#define TPB 256
#define TILES_PER_B (NN / TILE)   // 64

__device__ __align__(16) float g_P[DD*DD];
__device__ __align__(16) float g_slots[BB*SS*DD];
__device__ __align__(16) float g_h0[BB*DD];
__device__ __align__(16) float g_qp[BB*SS*DD];
__device__ __align__(16) float g_U[BB*SS*DD];
__device__ float g_Z[BB*SS];
__device__ __align__(16) float g_gi[BB*SS*3*DD];        // GRU input gates
__device__ __align__(16) __half g_xn[(long)BB*NN*DD];   // 64 MB LN(x) cache

// ---- k_attn smem layout (floats) ----
#define OFF_XN   0        // 256 rows * 9 f4 = 9216 fl (fp16 data)
#define OFF_PT   9216     // 256*8 probs fp32
#define OFF_QP   11264    // 112 f4 = 448 fl
#define OFF_PART 11712    // 4 warps * 7 * 64 = 1792 fl
#define OFF_Z    13504    // 112
#define ATTN_SMEM_BYTES ((13616)*4)

// ---- k_prep smem layout (floats) ----
#define P_IN  0           // 128 rows * 17 f4 = 8704 fl
#define P_OUT 8704        // 128 rows * 9 f4  = 4608 fl
#define P_G   13312
#define P_B   13376
#define PREP_SMEM_BYTES ((13440)*4)

// ---- k_upd2 smem layout (floats) ----
#define V_WHH 0           // 192*68 = 13056
#define V_W1  13056       // 128*68 = 8704
#define V_W2  21760       // 64*132 = 8448
#define V_GI  30208       // 1344
#define V_SL  31552       // 448
#define V_XB  32000       // 448
#define V_HID 32448       // 896
#define V_H   33344       // 64
#define V_GH  33408       // 192
#define V_M7  33600       // 8
#define V_R7  33608       // 8
#define UPD2_SMEM_BYTES ((33616)*4)

__device__ __forceinline__ void h8_to_f(const uint4& v, float* f) {
    const __half2* h = (const __half2*)&v;
    float2 t;
    t = __half22float2(h[0]); f[0]=t.x; f[1]=t.y;
    t = __half22float2(h[1]); f[2]=t.x; f[3]=t.y;
    t = __half22float2(h[2]); f[4]=t.x; f[5]=t.y;
    t = __half22float2(h[3]); f[6]=t.x; f[7]=t.y;
}
__device__ __forceinline__ unsigned pack_h2(float a, float b) {
    __half2 h = __float22half2_rn(make_float2(a, b));
    return *(unsigned*)&h;
}

// ---------------------------------------------------------------------------
// k_setup: blocks 0..31 -> slots/h0 init + zero U,Z.  block 32 -> P = Wq^T Wk
// ---------------------------------------------------------------------------
__global__ void k_setup(const float* __restrict__ mu, const float* __restrict__ lsig,
                        const float* __restrict__ nslots, const float* __restrict__ nh,
                        const float* __restrict__ Wq, const float* __restrict__ Wk) {
    int blk = blockIdx.x, tid = threadIdx.x;
    if (blk < BB) {
        int b = blk;
        for (int i = tid; i < SS*DD; i += blockDim.x) {
            int d = i & (DD-1);
            float sg = __expf(lsig[d]);
            g_slots[b*SS*DD + i] = mu[d] + sg * nslots[b*SS*DD + i];
            g_U[b*SS*DD + i] = 0.f;
        }
        for (int d = tid; d < DD; d += blockDim.x) {
            float sg = __expf(lsig[d]);
            g_h0[b*DD + d] = mu[d] + sg * nh[b*DD + d];
        }
        if (tid < SS) g_Z[b*SS + tid] = 0.f;
    } else {
        __shared__ float sq[DD*DD], sk[DD*DD];
        for (int i = tid; i < DD*DD; i += blockDim.x) { sq[i] = Wq[i]; sk[i] = Wk[i]; }
        __syncthreads();
        for (int i = tid; i < DD*DD; i += blockDim.x) {
            int dp = i >> 6, d = i & 63;
            float acc = 0.f;
            for (int e = 0; e < DD; e++) acc += sq[e*DD+dp] * sk[e*DD+d];
            g_P[i] = acc;
        }
    }
}

// ---------------------------------------------------------------------------
// k_prep: LN(inputs) -> g_xn (fp16), coalesced in & out via smem bounce
// ---------------------------------------------------------------------------
__global__ __launch_bounds__(256)
void k_prep(const float* __restrict__ x_in,
            const float* __restrict__ lg, const float* __restrict__ lb) {
    extern __shared__ __align__(16) float sp[];
    float4* s_in  = (float4*)(sp + P_IN);      // [128][17]
    uint4*  s_out = (uint4*)(sp + P_OUT);      // [128][9]
    float*  s_g   = sp + P_G;
    float*  s_b   = sp + P_B;
    int tid = threadIdx.x;
    long row_base = (long)blockIdx.x * 128;

    if (tid < DD) { s_g[tid] = lg[tid]; s_b[tid] = lb[tid]; }
    const float4* gin = (const float4*)x_in + row_base*16;
#pragma unroll
    for (int jj = 0; jj < 8; jj++) {
        int li = jj*256 + tid;
        s_in[(li>>4)*17 + (li&15)] = gin[li];
    }
    __syncthreads();

    if (tid < 128) {
        const float4* xr = s_in + tid*17;
        float4 x[16];
#pragma unroll
        for (int j = 0; j < 16; j++) x[j] = xr[j];
        float sm = 0.f, sq = 0.f;
#pragma unroll
        for (int j = 0; j < 16; j++) {
            sm += x[j].x + x[j].y + x[j].z + x[j].w;
            sq += x[j].x*x[j].x + x[j].y*x[j].y + x[j].z*x[j].z + x[j].w*x[j].w;
        }
        float m = sm * (1.f/DD);
        float rstd = rsqrtf(sq*(1.f/DD) - m*m + 1e-5f);
#pragma unroll
        for (int j = 0; j < 8; j++) {
            float4 a = x[2*j], c = x[2*j+1];
            float n0 = (a.x-m)*rstd*s_g[8*j+0] + s_b[8*j+0];
            float n1 = (a.y-m)*rstd*s_g[8*j+1] + s_b[8*j+1];
            float n2 = (a.z-m)*rstd*s_g[8*j+2] + s_b[8*j+2];
            float n3 = (a.w-m)*rstd*s_g[8*j+3] + s_b[8*j+3];
            float n4 = (c.x-m)*rstd*s_g[8*j+4] + s_b[8*j+4];
            float n5 = (c.y-m)*rstd*s_g[8*j+5] + s_b[8*j+5];
            float n6 = (c.z-m)*rstd*s_g[8*j+6] + s_b[8*j+6];
            float n7 = (c.w-m)*rstd*s_g[8*j+7] + s_b[8*j+7];
            uint4 o;
            o.x = pack_h2(n0, n1);
            o.y = pack_h2(n2, n3);
            o.z = pack_h2(n4, n5);
            o.w = pack_h2(n6, n7);
            s_out[tid*9 + j] = o;
        }
    }
    __syncthreads();

    uint4* gout = (uint4*)g_xn + row_base*8;
#pragma unroll
    for (int jj = 0; jj < 4; jj++) {
        int li = jj*256 + tid;
        gout[li] = s_out[(li>>3)*9 + (li&7)];
    }
}

// ---------------------------------------------------------------------------
// k_qp0: q'[b,s,:] = scale * LN_slots(slots[b,s]) @ P
// ---------------------------------------------------------------------------
__global__ void k_qp0(const float* __restrict__ lsg, const float* __restrict__ lsb) {
    int b = blockIdx.x, tid = threadIdx.x;
    __shared__ float sl[SS*DD], sn[SS*DD], m7[SS], r7[SS];
    for (int i = tid; i < SS*DD; i += blockDim.x) sl[i] = g_slots[b*SS*DD+i];
    __syncthreads();
    if (tid < SS) {
        float sm = 0.f, sq = 0.f;
        for (int d = 0; d < DD; d++) { float v = sl[tid*DD+d]; sm += v; sq += v*v; }
        float m = sm * (1.f/DD);
        m7[tid] = m;
        r7[tid] = rsqrtf(sq*(1.f/DD) - m*m + 1e-5f);
    }
    __syncthreads();
    for (int i = tid; i < SS*DD; i += blockDim.x) {
        int s = i >> 6, d = i & 63;
        sn[i] = (sl[i]-m7[s])*r7[s]*lsg[d] + lsb[d];
    }
    __syncthreads();
    for (int o = tid; o < SS*DD; o += blockDim.x) {
        int s = o >> 6, d = o & 63;
        float acc = 0.f;
        for (int dp = 0; dp < DD; dp++) acc += sn[s*DD+dp] * g_P[dp*DD+d];
        g_qp[b*SS*DD+o] = 0.125f * acc;
    }
}

// ---------------------------------------------------------------------------
// k_attn: logits -> softmax -> outer product; 16 groups -> warp-shfl merge
// to 4 partials -> smem merge -> global REDs.
// ---------------------------------------------------------------------------
__global__ __launch_bounds__(TPB, 3)
void k_attn() {
    extern __shared__ __align__(16) float smem[];
    uint4*  s_xn4   = (uint4*)(smem + OFF_XN);     // [256][9] fp16 rows
    float*  s_pT    = smem + OFF_PT;               // [256][8] probs fp32
    float4* s_qp4   = (float4*)(smem + OFF_QP);    // [7][16]
    float*  s_part  = smem + OFF_PART;             // [4][7][64]
    float4* s_part4 = (float4*)s_part;
    float*  s_z     = smem + OFF_Z;                // [7][16]

    int b   = blockIdx.x >> 6;
    int rb  = (blockIdx.x & (TILES_PER_B-1)) * TILE;
    int tid = threadIdx.x;

    // phase 0: coalesced tile copy + q' load
    {
        const uint4* gx = (const uint4*)g_xn + ((long)b*NN + rb)*8;
#pragma unroll
        for (int jj = 0; jj < 8; jj++) {
            int li = jj*256 + tid;
            s_xn4[(li>>3)*9 + (li&7)] = gx[li];
        }
        for (int i = tid; i < SS*DD/4; i += TPB)
            s_qp4[i] = ((const float4*)(g_qp + b*SS*DD))[i];
    }
    __syncthreads();

    // phase 1: one row per thread -> logits -> softmax -> probs (fp32)
    {
        const uint4* xr = s_xn4 + tid*9;
        float acc[SS];
#pragma unroll
        for (int s = 0; s < SS; s++) acc[s] = 0.f;
#pragma unroll
        for (int j = 0; j < 8; j++) {
            uint4 xv = xr[j];
            float xf[8]; h8_to_f(xv, xf);
#pragma unroll
            for (int s = 0; s < SS; s++) {
                float4 qa = s_qp4[s*16 + 2*j];
                float4 qb = s_qp4[s*16 + 2*j + 1];
                acc[s] += xf[0]*qa.x + xf[1]*qa.y + xf[2]*qa.z + xf[3]*qa.w
                        + xf[4]*qb.x + xf[5]*qb.y + xf[6]*qb.z + xf[7]*qb.w;
            }
        }
        float mx = acc[0];
#pragma unroll
        for (int s = 1; s < SS; s++) mx = fmaxf(mx, acc[s]);
        float es[SS], se = 0.f;
#pragma unroll
        for (int s = 0; s < SS; s++) { es[s] = __expf(acc[s]-mx); se += es[s]; }
        float inv = 1.f/se;
        float4* pr = (float4*)(s_pT + tid*8);
        pr[0] = make_float4(es[0]*inv+1e-8f, es[1]*inv+1e-8f,
                            es[2]*inv+1e-8f, es[3]*inv+1e-8f);
        pr[1] = make_float4(es[4]*inv+1e-8f, es[5]*inv+1e-8f,
                            es[6]*inv+1e-8f, 0.f);
    }
    __syncthreads();

    // phase 2a: 16 row-groups x 8 d-chunks; then warp-shfl merge 4 groups
    if (tid < 128) {
        int g = tid >> 3, dc = tid & 7;
        int r0 = g*16;
        float a[SS][8];
#pragma unroll
        for (int s = 0; s < SS; s++)
#pragma unroll
            for (int k = 0; k < 8; k++) a[s][k] = 0.f;
#pragma unroll 4
        for (int rr = 0; rr < 16; rr++) {
            int r = r0 + rr;
            uint4 xv = s_xn4[r*9 + dc];
            float xf[8]; h8_to_f(xv, xf);
            float4 pA = *(const float4*)(s_pT + r*8);
            float4 pB = *(const float4*)(s_pT + r*8 + 4);
            float p[SS] = {pA.x, pA.y, pA.z, pA.w, pB.x, pB.y, pB.z};
#pragma unroll
            for (int s = 0; s < SS; s++)
#pragma unroll
                for (int k = 0; k < 8; k++) a[s][k] += p[s]*xf[k];
        }
        // merge the 4 groups held by this warp (lane bits 3,4)
#pragma unroll
        for (int s = 0; s < SS; s++)
#pragma unroll
            for (int k = 0; k < 8; k++) {
                a[s][k] += __shfl_xor_sync(0xffffffffu, a[s][k], 8);
                a[s][k] += __shfl_xor_sync(0xffffffffu, a[s][k], 16);
            }
        if ((tid & 24) == 0) {                      // 8 lanes per warp survive
            int w = tid >> 5;
#pragma unroll
            for (int s = 0; s < SS; s++) {
                float* dst = s_part + (w*SS + s)*64 + dc*8;
                *(float4*)dst     = make_float4(a[s][0],a[s][1],a[s][2],a[s][3]);
                *(float4*)(dst+4) = make_float4(a[s][4],a[s][5],a[s][6],a[s][7]);
            }
        }
    } else if (tid < 128 + 112) {                   // Z partials
        int t = tid - 128, s = t >> 4, g = t & 15;
        float z = 0.f;
#pragma unroll 4
        for (int rr = 0; rr < 16; rr++) z += s_pT[(g*16+rr)*8 + s];
        s_z[s*16 + g] = z;
    }
    __syncthreads();

    // phase 2b: merge 4 partials, one RED per output
    if (tid < SS*16) {
        int s = tid >> 4, dq = tid & 15;
        float4 p0 = s_part4[(0*SS+s)*16+dq], p1 = s_part4[(1*SS+s)*16+dq];
        float4 p2 = s_part4[(2*SS+s)*16+dq], p3 = s_part4[(3*SS+s)*16+dq];
        float4 r;
        r.x = (p0.x+p1.x)+(p2.x+p3.x); r.y = (p0.y+p1.y)+(p2.y+p3.y);
        r.z = (p0.z+p1.z)+(p2.z+p3.z); r.w = (p0.w+p1.w)+(p2.w+p3.w);
        float* up = g_U + (b*SS + s)*DD + dq*4;
        atomicAdd(up+0, r.x); atomicAdd(up+1, r.y);
        atomicAdd(up+2, r.z); atomicAdd(up+3, r.w);
    } else if (tid < SS*16 + SS) {
        int s = tid - SS*16;
        float z = 0.f;
#pragma unroll
        for (int g = 0; g < 16; g++) z += s_z[s*16+g];
        atomicAdd(&g_Z[b*SS+s], z);
    }
}

// ---------------------------------------------------------------------------
// k_upd1: per (b,s): updates = (U . Wv^T)/Z, then gi = upd @ w_ih^T + b_ih
// ---------------------------------------------------------------------------
__global__ __launch_bounds__(192)
void k_upd1(const float* __restrict__ Wv,
            const float* __restrict__ w_ih, const float* __restrict__ b_ih) {
    int blk = blockIdx.x;           // 0..223
    int b = blk / SS, s = blk - b*SS;
    int tid = threadIdx.x;
    __shared__ float sU[DD], supd[DD];
    __shared__ float sZ;

    if (tid < DD) sU[tid] = g_U[(b*SS+s)*DD + tid];
    if (tid == 0) sZ = g_Z[b*SS+s];
    __syncthreads();

    if (tid < DD) {
        const float4* w = (const float4*)(Wv + tid*DD);
        const float4* u = (const float4*)sU;
        float a0=0,a1=0,a2=0,a3=0;
#pragma unroll
        for (int j = 0; j < 16; j++) {
            float4 a = u[j], c = w[j];
            a0 += a.x*c.x; a1 += a.y*c.y; a2 += a.z*c.z; a3 += a.w*c.w;
        }
        supd[tid] = ((a0+a1)+(a2+a3)) / sZ;
    }
    __syncthreads();

    {
        const float4* w = (const float4*)(w_ih + tid*DD);
        const float4* u = (const float4*)supd;
        float a0=b_ih[tid],a1=0,a2=0,a3=0;
#pragma unroll
        for (int j = 0; j < 16; j++) {
            float4 a = u[j], c = w[j];
            a0 += a.x*c.x; a1 += a.y*c.y; a2 += a.z*c.z; a3 += a.w*c.w;
        }
        g_gi[(b*SS+s)*3*DD + tid] = (a0+a1)+(a2+a3);
    }
}

// ---------------------------------------------------------------------------
// k_upd2: GRU over slots (smem-staged weights) -> MLP -> slots + next q'
// ---------------------------------------------------------------------------
__global__ __launch_bounds__(256)
void k_upd2(const float* __restrict__ w_hh, const float* __restrict__ b_hh,
            const float* __restrict__ w1, const float* __restrict__ b1,
            const float* __restrict__ w2, const float* __restrict__ b2,
            const float* __restrict__ lsg, const float* __restrict__ lsb,
            const float* __restrict__ lmg, const float* __restrict__ lmb,
            float* __restrict__ dout, int last) {
    extern __shared__ __align__(16) float sm[];
    float* whh = sm + V_WHH;     // [192][68]
    float* w1s = sm + V_W1;      // [128][68]
    float* w2s = sm + V_W2;      // [64][132]
    float* gis = sm + V_GI;      // [7][192]
    float* sl  = sm + V_SL;      // [7][64]
    float* xb  = sm + V_XB;
    float* hid = sm + V_HID;     // [7][128]
    float* h   = sm + V_H;
    float* ghs = sm + V_GH;      // [192]
    float* m7  = sm + V_M7;
    float* r7  = sm + V_R7;

    int b = blockIdx.x, tid = threadIdx.x;

    for (int i = tid; i < 3*DD*DD; i += 256) { int r = i>>6, e = i&63; whh[r*68+e] = w_hh[i]; }
    for (int i = tid; i < HH*DD;   i += 256) { int r = i>>6, e = i&63; w1s[r*68+e] = w1[i]; }
    for (int i = tid; i < DD*HH;   i += 256) { int r = i>>7, k = i&127; w2s[r*132+k] = w2[i]; }
    for (int i = tid; i < SS*3*DD; i += 256) gis[i] = g_gi[b*SS*3*DD + i];
    if (tid < DD) h[tid] = g_h0[b*DD+tid];
    __syncthreads();

    // GRU over slot axis
    for (int s = 0; s < SS; s++) {
        if (tid < 3*DD) {
            const float4* w = (const float4*)(whh + tid*68);
            const float4* hv = (const float4*)h;
            float a0=b_hh[tid],a1=0,a2=0,a3=0;
#pragma unroll
            for (int j = 0; j < 16; j++) {
                float4 c = w[j], a = hv[j];
                a0 += a.x*c.x; a1 += a.y*c.y; a2 += a.z*c.z; a3 += a.w*c.w;
            }
            ghs[tid] = (a0+a1)+(a2+a3);
        }
        __syncthreads();
        if (tid < DD) {
            float r = 1.f/(1.f + __expf(-(gis[s*192+tid]     + ghs[tid])));
            float z = 1.f/(1.f + __expf(-(gis[s*192+64+tid]  + ghs[64+tid])));
            float nx = gis[s*192+128+tid] + r*ghs[128+tid];
            float n = 1.f - 2.f/(__expf(2.f*nx) + 1.f);   // tanh
            float hn = (1.f-z)*n + z*h[tid];
            h[tid] = hn;
            sl[s*DD+tid] = hn;
        }
        __syncthreads();
    }

    // MLP: slots += relu(LN_mlp(slots) @ w1^T + b1) @ w2^T + b2
    if (tid < SS) {
        float smv = 0.f, sq = 0.f;
        for (int d = 0; d < DD; d++) { float v = sl[tid*DD+d]; smv += v; sq += v*v; }
        float m = smv*(1.f/DD);
        m7[tid] = m; r7[tid] = rsqrtf(sq*(1.f/DD) - m*m + 1e-5f);
    }
    __syncthreads();
    for (int i = tid; i < SS*DD; i += 256) {
        int s = i >> 6, d = i & 63;
        xb[i] = (sl[i]-m7[s])*r7[s]*lmg[d] + lmb[d];
    }
    __syncthreads();
    for (int o = tid; o < SS*HH; o += 256) {
        int s = o >> 7, hc = o & 127;
        const float4* w = (const float4*)(w1s + hc*68);
        const float4* u = (const float4*)(xb + s*DD);
        float a0=b1[hc],a1=0,a2=0,a3=0;
#pragma unroll
        for (int j = 0; j < 16; j++) {
            float4 a = u[j], c = w[j];
            a0 += a.x*c.x; a1 += a.y*c.y; a2 += a.z*c.z; a3 += a.w*c.w;
        }
        hid[o] = fmaxf((a0+a1)+(a2+a3), 0.f);
    }
    __syncthreads();
    for (int o = tid; o < SS*DD; o += 256) {
        int s = o >> 6, d = o & 63;
        const float4* w = (const float4*)(w2s + d*132);
        const float4* u = (const float4*)(hid + s*HH);
        float a0=b2[d],a1=0,a2=0,a3=0;
#pragma unroll
        for (int j = 0; j < 32; j++) {
            float4 a = u[j], c = w[j];
            a0 += a.x*c.x; a1 += a.y*c.y; a2 += a.z*c.z; a3 += a.w*c.w;
        }
        float v = sl[o] + (a0+a1)+(a2+a3);
        sl[o] = v;                     // new slots
        g_slots[b*SS*DD+o] = v;
        dout[b*SS*DD+o] = v;
    }
    __syncthreads();

    if (!last) {
        if (tid < SS) {
            float smv = 0.f, sq = 0.f;
            for (int d = 0; d < DD; d++) { float v = sl[tid*DD+d]; smv += v; sq += v*v; }
            float m = smv*(1.f/DD);
            m7[tid] = m; r7[tid] = rsqrtf(sq*(1.f/DD) - m*m + 1e-5f);
        }
        __syncthreads();
        for (int i = tid; i < SS*DD; i += 256) {
            int s = i >> 6, d = i & 63;
            xb[i] = (sl[i]-m7[s])*r7[s]*lsg[d] + lsb[d];
        }
        __syncthreads();
        for (int o = tid; o < SS*DD; o += 256) {
            int s = o >> 6, d = o & 63;
            float a0=0,a1=0,a2=0,a3=0;
#pragma unroll
            for (int dp = 0; dp < DD; dp += 4) {
                a0 += xb[s*DD+dp+0]*g_P[(dp+0)*DD+d];
                a1 += xb[s*DD+dp+1]*g_P[(dp+1)*DD+d];
                a2 += xb[s*DD+dp+2]*g_P[(dp+2)*DD+d];
                a3 += xb[s*DD+dp+3]*g_P[(dp+3)*DD+d];
            }
            g_qp[b*SS*DD+o] = 0.125f*((a0+a1)+(a2+a3));
            g_U[b*SS*DD+o] = 0.f;
        }
        if (tid < SS) g_Z[b*SS+tid] = 0.f;
    }
}

// ---------------------------------------------------------------------------
extern "C" void kernel_launch(void* const* d_in, const int* in_sizes, int n_in,
                              void* d_out, int out_size) {
    const float* inputs     = (const float*)d_in[0];
    const float* ln_in_g    = (const float*)d_in[1];
    const float* ln_in_b    = (const float*)d_in[2];
    const float* ln_slots_g = (const float*)d_in[3];
    const float* ln_slots_b = (const float*)d_in[4];
    const float* ln_mlp_g   = (const float*)d_in[5];
    const float* ln_mlp_b   = (const float*)d_in[6];
    const float* Wq         = (const float*)d_in[7];
    const float* Wk         = (const float*)d_in[8];
    const float* Wv         = (const float*)d_in[9];
    const float* mu         = (const float*)d_in[10];
    const float* lsig       = (const float*)d_in[11];
    const float* w_ih       = (const float*)d_in[12];
    const float* w_hh       = (const float*)d_in[13];
    const float* b_ih       = (const float*)d_in[14];
    const float* b_hh       = (const float*)d_in[15];
    const float* w1         = (const float*)d_in[16];
    const float* b1         = (const float*)d_in[17];
    const float* w2         = (const float*)d_in[18];
    const float* b2         = (const float*)d_in[19];
    const float* nslots     = (const float*)d_in[20];
    const float* nh         = (const float*)d_in[21];
    float* out = (float*)d_out;

    cudaFuncSetAttribute(k_prep,  cudaFuncAttributeMaxDynamicSharedMemorySize, PREP_SMEM_BYTES);
    cudaFuncSetAttribute(k_attn,  cudaFuncAttributeMaxDynamicSharedMemorySize, ATTN_SMEM_BYTES);
    cudaFuncSetAttribute(k_upd2,  cudaFuncAttributeMaxDynamicSharedMemorySize, UPD2_SMEM_BYTES);

    k_setup<<<BB+1, 256>>>(mu, lsig, nslots, nh, Wq, Wk);
    k_prep<<<(BB*NN)/128, 256, PREP_SMEM_BYTES>>>(inputs, ln_in_g, ln_in_b);
    k_qp0<<<BB, 256>>>(ln_slots_g, ln_slots_b);
    for (int it = 0; it < 3; it++) {
        k_attn<<<BB*TILES_PER_B, TPB, ATTN_SMEM_BYTES>>>();
        k_upd1<<<BB*SS, 192>>>(Wv, w_ih, b_ih);
        k_upd2<<<BB, 256, UPD2_SMEM_BYTES>>>(w_hh, b_hh, w1, b1, w2, b2,
                                             ln_slots_g, ln_slots_b, ln_mlp_g, ln_mlp_b,
                                             out, it == 2);
    }
}

// round 8
// speedup vs baseline: 1.7882x; 1.1390x over previous
#include <cuda_runtime.h>
#include <cuda_fp16.h>
#include <math.h>

#define BB 32
#define NN 16384
#define DD 64
#define SS 7
#define HH 128
#define TILE 256
#define TPB 256
#define TILES_PER_B (NN / TILE)   // 64

__device__ __align__(16) float g_P[DD*DD];
__device__ __align__(16) float g_slots[BB*SS*DD];
__device__ __align__(16) float g_h0[BB*DD];
__device__ __align__(16) float g_qp[BB*SS*DD];
__device__ __align__(16) float g_U[BB*SS*DD];
__device__ float g_Z[BB*SS];
__device__ __align__(16) float g_Sx[BB*DD];             // sum_n xn (for eps fold)
__device__ __align__(16) float g_gi[BB*SS*3*DD];        // GRU input gates
__device__ __align__(16) __half g_xn[(long)BB*NN*DD];   // 64 MB LN(x) cache

// ---- k_attn smem layout (bytes) ----
#define A_XN    0        // 256 rows * 72 halves = 36864 B
#define A_QPH   36864    // 8 * 72 halves = 1152 B
#define A_PT    38016    // 8 * 264 halves = 4224 B
#define A_PART  42240    // 2 * 64 * 8 fp32 = 4096 B
#define ATTN_SMEM_BYTES 46336

// ---- k_prep smem layout (floats) ----
#define P_IN  0           // 128 rows * 17 f4 = 8704 fl
#define P_OUT 8704        // 128 rows * 9 f4  = 4608 fl
#define P_G   13312
#define P_B   13376
#define PREP_SMEM_BYTES ((13440)*4)

// ---- k_upd2 smem layout (floats) ----
#define V_WHH 0           // 192*68 = 13056
#define V_GI  13056       // 1344
#define V_SL  14400       // 448
#define V_XB  14848       // 448
#define V_HID 15296       // 896
#define V_H   16192       // 64
#define V_GH  16256       // 192
#define V_M7  16448       // 8
#define V_R7  16456       // 8
#define UPD2_SMEM_BYTES ((16464)*4)

__device__ __forceinline__ unsigned pack_h2(float a, float b) {
    __half2 h = __float22half2_rn(make_float2(a, b));
    return *(unsigned*)&h;
}

#define LDSM_X4(a0,a1,a2,a3,addr) \
    asm volatile("ldmatrix.sync.aligned.m8n8.x4.shared.b16 {%0,%1,%2,%3}, [%4];" \
        : "=r"(a0),"=r"(a1),"=r"(a2),"=r"(a3) : "r"(addr))
#define LDSM_X4_T(a0,a1,a2,a3,addr) \
    asm volatile("ldmatrix.sync.aligned.m8n8.x4.trans.shared.b16 {%0,%1,%2,%3}, [%4];" \
        : "=r"(a0),"=r"(a1),"=r"(a2),"=r"(a3) : "r"(addr))
#define MMA16816(c0,c1,c2,c3,a0,a1,a2,a3,b0,b1) \
    asm volatile("mma.sync.aligned.m16n8k16.row.col.f32.f16.f16.f32 " \
        "{%0,%1,%2,%3}, {%4,%5,%6,%7}, {%8,%9}, {%0,%1,%2,%3};" \
        : "+f"(c0),"+f"(c1),"+f"(c2),"+f"(c3) \
        : "r"(a0),"r"(a1),"r"(a2),"r"(a3),"r"(b0),"r"(b1))

// ---------------------------------------------------------------------------
// k_setup: blocks 0..31 -> slots/h0 init + zero U,Z,Sx.  block 32 -> P=Wq^T Wk
// ---------------------------------------------------------------------------
__global__ void k_setup(const float* __restrict__ mu, const float* __restrict__ lsig,
                        const float* __restrict__ nslots, const float* __restrict__ nh,
                        const float* __restrict__ Wq, const float* __restrict__ Wk) {
    int blk = blockIdx.x, tid = threadIdx.x;
    if (blk < BB) {
        int b = blk;
        for (int i = tid; i < SS*DD; i += blockDim.x) {
            int d = i & (DD-1);
            float sg = __expf(lsig[d]);
            g_slots[b*SS*DD + i] = mu[d] + sg * nslots[b*SS*DD + i];
            g_U[b*SS*DD + i] = 0.f;
        }
        for (int d = tid; d < DD; d += blockDim.x) {
            float sg = __expf(lsig[d]);
            g_h0[b*DD + d] = mu[d] + sg * nh[b*DD + d];
            g_Sx[b*DD + d] = 0.f;
        }
        if (tid < SS) g_Z[b*SS + tid] = 0.f;
    } else {
        __shared__ float sq[DD*DD], sk[DD*DD];
        for (int i = tid; i < DD*DD; i += blockDim.x) { sq[i] = Wq[i]; sk[i] = Wk[i]; }
        __syncthreads();
        for (int i = tid; i < DD*DD; i += blockDim.x) {
            int dp = i >> 6, d = i & 63;
            float acc = 0.f;
            for (int e = 0; e < DD; e++) acc += sq[e*DD+dp] * sk[e*DD+d];
            g_P[i] = acc;
        }
    }
}

// ---------------------------------------------------------------------------
// k_prep: LN(inputs) -> g_xn (fp16) + per-batch column sums Sx
// ---------------------------------------------------------------------------
__global__ __launch_bounds__(256)
void k_prep(const float* __restrict__ x_in,
            const float* __restrict__ lg, const float* __restrict__ lb) {
    extern __shared__ __align__(16) float sp[];
    float4* s_in  = (float4*)(sp + P_IN);      // [128][17]
    uint4*  s_out = (uint4*)(sp + P_OUT);      // [128][9]
    float*  s_g   = sp + P_G;
    float*  s_b   = sp + P_B;
    int tid = threadIdx.x;
    long row_base = (long)blockIdx.x * 128;
    int b = blockIdx.x >> 7;                   // NN/128 = 128 blocks per batch

    if (tid < DD) { s_g[tid] = lg[tid]; s_b[tid] = lb[tid]; }
    const float4* gin = (const float4*)x_in + row_base*16;
#pragma unroll
    for (int jj = 0; jj < 8; jj++) {
        int li = jj*256 + tid;
        s_in[(li>>4)*17 + (li&15)] = gin[li];
    }
    __syncthreads();

    if (tid < 128) {
        const float4* xr = s_in + tid*17;
        float4 x[16];
#pragma unroll
        for (int j = 0; j < 16; j++) x[j] = xr[j];
        float sm = 0.f, sq = 0.f;
#pragma unroll
        for (int j = 0; j < 16; j++) {
            sm += x[j].x + x[j].y + x[j].z + x[j].w;
            sq += x[j].x*x[j].x + x[j].y*x[j].y + x[j].z*x[j].z + x[j].w*x[j].w;
        }
        float m = sm * (1.f/DD);
        float rstd = rsqrtf(sq*(1.f/DD) - m*m + 1e-5f);
#pragma unroll
        for (int j = 0; j < 8; j++) {
            float4 a = x[2*j], c = x[2*j+1];
            float n0 = (a.x-m)*rstd*s_g[8*j+0] + s_b[8*j+0];
            float n1 = (a.y-m)*rstd*s_g[8*j+1] + s_b[8*j+1];
            float n2 = (a.z-m)*rstd*s_g[8*j+2] + s_b[8*j+2];
            float n3 = (a.w-m)*rstd*s_g[8*j+3] + s_b[8*j+3];
            float n4 = (c.x-m)*rstd*s_g[8*j+4] + s_b[8*j+4];
            float n5 = (c.y-m)*rstd*s_g[8*j+5] + s_b[8*j+5];
            float n6 = (c.z-m)*rstd*s_g[8*j+6] + s_b[8*j+6];
            float n7 = (c.w-m)*rstd*s_g[8*j+7] + s_b[8*j+7];
            uint4 o;
            o.x = pack_h2(n0, n1);
            o.y = pack_h2(n2, n3);
            o.z = pack_h2(n4, n5);
            o.w = pack_h2(n6, n7);
            s_out[tid*9 + j] = o;
        }
    }
    __syncthreads();

    uint4* gout = (uint4*)g_xn + row_base*8;
#pragma unroll
    for (int jj = 0; jj < 4; jj++) {
        int li = jj*256 + tid;
        gout[li] = s_out[(li>>3)*9 + (li&7)];
    }
    // column sums of this block's 128 normalized rows (fp16-consistent)
    if (tid < DD) {
        const __half* hp = (const __half*)s_out;
        float acc = 0.f;
        for (int r = 0; r < 128; r++) acc += __half2float(hp[r*72 + tid]);
        atomicAdd(&g_Sx[b*DD + tid], acc);
    }
}

// ---------------------------------------------------------------------------
// k_qp0: q'[b,s,:] = scale * LN_slots(slots[b,s]) @ P
// ---------------------------------------------------------------------------
__global__ void k_qp0(const float* __restrict__ lsg, const float* __restrict__ lsb) {
    int b = blockIdx.x, tid = threadIdx.x;
    __shared__ float sl[SS*DD], sn[SS*DD], m7[SS], r7[SS];
    for (int i = tid; i < SS*DD; i += blockDim.x) sl[i] = g_slots[b*SS*DD+i];
    __syncthreads();
    if (tid < SS) {
        float sm = 0.f, sq = 0.f;
        for (int d = 0; d < DD; d++) { float v = sl[tid*DD+d]; sm += v; sq += v*v; }
        float m = sm * (1.f/DD);
        m7[tid] = m;
        r7[tid] = rsqrtf(sq*(1.f/DD) - m*m + 1e-5f);
    }
    __syncthreads();
    for (int i = tid; i < SS*DD; i += blockDim.x) {
        int s = i >> 6, d = i & 63;
        sn[i] = (sl[i]-m7[s])*r7[s]*lsg[d] + lsb[d];
    }
    __syncthreads();
    for (int o = tid; o < SS*DD; o += blockDim.x) {
        int s = o >> 6, d = o & 63;
        float acc = 0.f;
        for (int dp = 0; dp < DD; dp++) acc += sn[s*DD+dp] * g_P[dp*DD+d];
        g_qp[b*SS*DD+o] = 0.125f * acc;
    }
}

// ---------------------------------------------------------------------------
// k_attn (HMMA): GEMM1 logits -> softmax -> GEMM2 U accumulation
// ---------------------------------------------------------------------------
__global__ __launch_bounds__(TPB)
void k_attn() {
    extern __shared__ __align__(16) char smem[];
    uint4*  s_xn4 = (uint4*)(smem + A_XN);       // [256][9] fp16 rows, pitch 72 halves
    __half* qph   = (__half*)(smem + A_QPH);     // [8][72]
    __half* pT    = (__half*)(smem + A_PT);      // [8][264]
    float*  part  = (float*)(smem + A_PART);     // [2][64][8]

    int b   = blockIdx.x >> 6;
    int rb  = (blockIdx.x & (TILES_PER_B-1)) * TILE;
    int tid = threadIdx.x;
    int w   = tid >> 5, l = tid & 31;

    // ---- phase 0: tile copy + q' -> fp16 ----
    {
        const uint4* gx = (const uint4*)g_xn + ((long)b*NN + rb)*8;
#pragma unroll
        for (int jj = 0; jj < 8; jj++) {
            int li = jj*256 + tid;
            s_xn4[(li>>3)*9 + (li&7)] = gx[li];
        }
        int n = tid >> 5, kp = tid & 31;
        float2 v = (n < 7) ? ((const float2*)(g_qp + b*SS*DD + n*DD))[kp]
                           : make_float2(0.f, 0.f);
        *(unsigned*)(qph + n*72 + kp*2) = pack_h2(v.x, v.y);
    }
    __syncthreads();

    unsigned xn_sa = (unsigned)__cvta_generic_to_shared(smem + A_XN);
    int e   = 2*(l & 3);          // C-frag / B-frag k-pair col
    int gid = l >> 2;
    bool lastc = (l & 3) == 3;

    // ---- phase 1: GEMM1 + softmax -> pT (fp16), Z (fp32) ----
    float zacc0 = 0.f, zacc1 = 0.f;
    {
        int arow = (l & 15);
        int acol = (l >> 4) << 3;
#pragma unroll
        for (int mt = 0; mt < 2; mt++) {
            int r0 = w*32 + mt*16;
            float c0=0.f,c1=0.f,c2=0.f,c3=0.f;
#pragma unroll
            for (int kk = 0; kk < 4; kk++) {
                unsigned addr = xn_sa + (unsigned)(((r0 + arow)*72 + kk*16 + acol)*2);
                unsigned a0,a1,a2,a3;
                LDSM_X4(a0,a1,a2,a3, addr);
                unsigned b0 = *(const unsigned*)(qph + gid*72 + kk*16 + e);
                unsigned b1 = *(const unsigned*)(qph + gid*72 + kk*16 + e + 8);
                MMA16816(c0,c1,c2,c3, a0,a1,a2,a3, b0,b1);
            }
            int rA = r0 + gid, rB = rA + 8;
            float v1 = lastc ? -1e30f : c1;
            float v3 = lastc ? -1e30f : c3;
            float m0 = fmaxf(c0, v1), m1 = fmaxf(c2, v3);
            m0 = fmaxf(m0, __shfl_xor_sync(0xffffffffu, m0, 1));
            m0 = fmaxf(m0, __shfl_xor_sync(0xffffffffu, m0, 2));
            m1 = fmaxf(m1, __shfl_xor_sync(0xffffffffu, m1, 1));
            m1 = fmaxf(m1, __shfl_xor_sync(0xffffffffu, m1, 2));
            float e0 = __expf(c0 - m0), e1 = lastc ? 0.f : __expf(c1 - m0);
            float e2 = __expf(c2 - m1), e3 = lastc ? 0.f : __expf(c3 - m1);
            float s0 = e0 + e1, s1 = e2 + e3;
            s0 += __shfl_xor_sync(0xffffffffu, s0, 1);
            s0 += __shfl_xor_sync(0xffffffffu, s0, 2);
            s1 += __shfl_xor_sync(0xffffffffu, s1, 1);
            s1 += __shfl_xor_sync(0xffffffffu, s1, 2);
            float p0 = e0/s0, p1 = e1/s0, p2 = e2/s1, p3 = e3/s1;
            pT[e*264 + rA]     = __float2half_rn(p0);
            pT[(e+1)*264 + rA] = __float2half_rn(p1);
            pT[e*264 + rB]     = __float2half_rn(p2);
            pT[(e+1)*264 + rB] = __float2half_rn(p3);
            zacc0 += p0 + p2; zacc1 += p1 + p3;
        }
    }
    zacc0 += __shfl_xor_sync(0xffffffffu, zacc0, 4);
    zacc0 += __shfl_xor_sync(0xffffffffu, zacc0, 8);
    zacc0 += __shfl_xor_sync(0xffffffffu, zacc0, 16);
    zacc1 += __shfl_xor_sync(0xffffffffu, zacc1, 4);
    zacc1 += __shfl_xor_sync(0xffffffffu, zacc1, 8);
    zacc1 += __shfl_xor_sync(0xffffffffu, zacc1, 16);
    if (l < 4) {
        atomicAdd(&g_Z[b*SS + 2*l], zacc0);
        if (l < 3) atomicAdd(&g_Z[b*SS + 2*l + 1], zacc1);
    }
    __syncthreads();

    // ---- phase 2: GEMM2  U^T[64x8] = xn^T @ P ----
    {
        int mt = w & 3, kh = w >> 2;
        int d0 = mt*16;
        int R  = kh*128;
        float c0=0.f,c1=0.f,c2=0.f,c3=0.f;
        int trow = (l & 7) + ((l >> 4) << 3);
        int tcol = ((l >> 3) & 1) << 3;
#pragma unroll
        for (int kk = 0; kk < 8; kk++) {
            int k0 = R + kk*16;
            unsigned addr = xn_sa + (unsigned)(((k0 + trow)*72 + d0 + tcol)*2);
            unsigned a0,a1,a2,a3;
            LDSM_X4_T(a0,a1,a2,a3, addr);
            unsigned b0 = *(const unsigned*)(pT + gid*264 + k0 + e);
            unsigned b1 = *(const unsigned*)(pT + gid*264 + k0 + e + 8);
            MMA16816(c0,c1,c2,c3, a0,a1,a2,a3, b0,b1);
        }
        int dim = d0 + gid;
        float2* pp = (float2*)part;
        pp[kh*256 + dim*4 + (e>>1)]     = make_float2(c0, c1);
        pp[kh*256 + (dim+8)*4 + (e>>1)] = make_float2(c2, c3);
    }
    __syncthreads();
    // merge kh halves + global REDs (FIX: all 512 entries with 256 threads)
#pragma unroll
    for (int i = tid; i < 512; i += TPB) {
        int s = i & 7;
        if (s < 7) {
            int dim = i >> 3;
            float v = part[i] + part[512 + i];
            atomicAdd(&g_U[(b*SS + s)*DD + dim], v);
        }
    }
}

// ---------------------------------------------------------------------------
// k_upd1: per (b,s): updates = ((U + eps*Sx) . Wv^T)/(Z + N*eps), gi = ...
// ---------------------------------------------------------------------------
__global__ __launch_bounds__(192)
void k_upd1(const float* __restrict__ Wv,
            const float* __restrict__ w_ih, const float* __restrict__ b_ih) {
    int blk = blockIdx.x;           // 0..223
    int b = blk / SS, s = blk - b*SS;
    int tid = threadIdx.x;
    __shared__ float sU[DD], supd[DD];
    __shared__ float sZ;

    if (tid < DD) sU[tid] = g_U[(b*SS+s)*DD + tid] + 1e-8f * g_Sx[b*DD + tid];
    if (tid == 0) sZ = g_Z[b*SS+s] + 1.6384e-4f;   // + N*eps
    __syncthreads();

    if (tid < DD) {
        const float4* w = (const float4*)(Wv + tid*DD);
        const float4* u = (const float4*)sU;
        float a0=0,a1=0,a2=0,a3=0;
#pragma unroll
        for (int j = 0; j < 16; j++) {
            float4 a = u[j], c = w[j];
            a0 += a.x*c.x; a1 += a.y*c.y; a2 += a.z*c.z; a3 += a.w*c.w;
        }
        supd[tid] = ((a0+a1)+(a2+a3)) / sZ;
    }
    __syncthreads();

    {
        const float4* w = (const float4*)(w_ih + tid*DD);
        const float4* u = (const float4*)supd;
        float a0=b_ih[tid],a1=0,a2=0,a3=0;
#pragma unroll
        for (int j = 0; j < 16; j++) {
            float4 a = u[j], c = w[j];
            a0 += a.x*c.x; a1 += a.y*c.y; a2 += a.z*c.z; a3 += a.w*c.w;
        }
        g_gi[(b*SS+s)*3*DD + tid] = (a0+a1)+(a2+a3);
    }
}

// ---------------------------------------------------------------------------
// k_upd2: GRU over slots (whh staged) -> MLP -> slots + next q'
// ---------------------------------------------------------------------------
__global__ __launch_bounds__(256)
void k_upd2(const float* __restrict__ w_hh, const float* __restrict__ b_hh,
            const float* __restrict__ w1, const float* __restrict__ b1,
            const float* __restrict__ w2, const float* __restrict__ b2,
            const float* __restrict__ lsg, const float* __restrict__ lsb,
            const float* __restrict__ lmg, const float* __restrict__ lmb,
            float* __restrict__ dout, int last) {
    extern __shared__ __align__(16) float sm[];
    float* whh = sm + V_WHH;     // [192][68]
    float* gis = sm + V_GI;      // [7][192]
    float* sl  = sm + V_SL;      // [7][64]
    float* xb  = sm + V_XB;
    float* hid = sm + V_HID;     // [7][128]
    float* h   = sm + V_H;
    float* ghs = sm + V_GH;      // [192]
    float* m7  = sm + V_M7;
    float* r7  = sm + V_R7;

    int b = blockIdx.x, tid = threadIdx.x;

    for (int i = tid; i < 3*DD*DD; i += 256) { int r = i>>6, e = i&63; whh[r*68+e] = w_hh[i]; }
    for (int i = tid; i < SS*3*DD; i += 256) gis[i] = g_gi[b*SS*3*DD + i];
    if (tid < DD) h[tid] = g_h0[b*DD+tid];
    __syncthreads();

    for (int s = 0; s < SS; s++) {
        if (tid < 3*DD) {
            const float4* w = (const float4*)(whh + tid*68);
            const float4* hv = (const float4*)h;
            float a0=b_hh[tid],a1=0,a2=0,a3=0;
#pragma unroll
            for (int j = 0; j < 16; j++) {
                float4 c = w[j], a = hv[j];
                a0 += a.x*c.x; a1 += a.y*c.y; a2 += a.z*c.z; a3 += a.w*c.w;
            }
            ghs[tid] = (a0+a1)+(a2+a3);
        }
        __syncthreads();
        if (tid < DD) {
            float r = 1.f/(1.f + __expf(-(gis[s*192+tid]     + ghs[tid])));
            float z = 1.f/(1.f + __expf(-(gis[s*192+64+tid]  + ghs[64+tid])));
            float nx = gis[s*192+128+tid] + r*ghs[128+tid];
            float n = 1.f - 2.f/(__expf(2.f*nx) + 1.f);   // tanh
            float hn = (1.f-z)*n + z*h[tid];
            h[tid] = hn;
            sl[s*DD+tid] = hn;
        }
        __syncthreads();
    }

    if (tid < SS) {
        float smv = 0.f, sq = 0.f;
        for (int d = 0; d < DD; d++) { float v = sl[tid*DD+d]; smv += v; sq += v*v; }
        float m = smv*(1.f/DD);
        m7[tid] = m; r7[tid] = rsqrtf(sq*(1.f/DD) - m*m + 1e-5f);
    }
    __syncthreads();
    for (int i = tid; i < SS*DD; i += 256) {
        int s = i >> 6, d = i & 63;
        xb[i] = (sl[i]-m7[s])*r7[s]*lmg[d] + lmb[d];
    }
    __syncthreads();
    for (int o = tid; o < SS*HH; o += 256) {
        int s = o >> 7, hc = o & 127;
        const float4* w = (const float4*)(w1 + hc*DD);
        const float4* u = (const float4*)(xb + s*DD);
        float a0=b1[hc],a1=0,a2=0,a3=0;
#pragma unroll
        for (int j = 0; j < 16; j++) {
            float4 a = u[j], c = w[j];
            a0 += a.x*c.x; a1 += a.y*c.y; a2 += a.z*c.z; a3 += a.w*c.w;
        }
        hid[o] = fmaxf((a0+a1)+(a2+a3), 0.f);
    }
    __syncthreads();
    for (int o = tid; o < SS*DD; o += 256) {
        int s = o >> 6, d = o & 63;
        const float4* w = (const float4*)(w2 + d*HH);
        const float4* u = (const float4*)(hid + s*HH);
        float a0=b2[d],a1=0,a2=0,a3=0;
#pragma unroll
        for (int j = 0; j < 32; j++) {
            float4 a = u[j], c = w[j];
            a0 += a.x*c.x; a1 += a.y*c.y; a2 += a.z*c.z; a3 += a.w*c.w;
        }
        float v = sl[o] + (a0+a1)+(a2+a3);
        sl[o] = v;
        g_slots[b*SS*DD+o] = v;
        dout[b*SS*DD+o] = v;
    }
    __syncthreads();

    if (!last) {
        if (tid < SS) {
            float smv = 0.f, sq = 0.f;
            for (int d = 0; d < DD; d++) { float v = sl[tid*DD+d]; smv += v; sq += v*v; }
            float m = smv*(1.f/DD);
            m7[tid] = m; r7[tid] = rsqrtf(sq*(1.f/DD) - m*m + 1e-5f);
        }
        __syncthreads();
        for (int i = tid; i < SS*DD; i += 256) {
            int s = i >> 6, d = i & 63;
            xb[i] = (sl[i]-m7[s])*r7[s]*lsg[d] + lsb[d];
        }
        __syncthreads();
        for (int o = tid; o < SS*DD; o += 256) {
            int s = o >> 6, d = o & 63;
            float a0=0,a1=0,a2=0,a3=0;
#pragma unroll
            for (int dp = 0; dp < DD; dp += 4) {
                a0 += xb[s*DD+dp+0]*g_P[(dp+0)*DD+d];
                a1 += xb[s*DD+dp+1]*g_P[(dp+1)*DD+d];
                a2 += xb[s*DD+dp+2]*g_P[(dp+2)*DD+d];
                a3 += xb[s*DD+dp+3]*g_P[(dp+3)*DD+d];
            }
            g_qp[b*SS*DD+o] = 0.125f*((a0+a1)+(a2+a3));
            g_U[b*SS*DD+o] = 0.f;
        }
        if (tid < SS) g_Z[b*SS+tid] = 0.f;
    }
}

// ---------------------------------------------------------------------------
extern "C" void kernel_launch(void* const* d_in, const int* in_sizes, int n_in,
                              void* d_out, int out_size) {
    const float* inputs     = (const float*)d_in[0];
    const float* ln_in_g    = (const float*)d_in[1];
    const float* ln_in_b    = (const float*)d_in[2];
    const float* ln_slots_g = (const float*)d_in[3];
    const float* ln_slots_b = (const float*)d_in[4];
    const float* ln_mlp_g   = (const float*)d_in[5];
    const float* ln_mlp_b   = (const float*)d_in[6];
    const float* Wq         = (const float*)d_in[7];
    const float* Wk         = (const float*)d_in[8];
    const float* Wv         = (const float*)d_in[9];
    const float* mu         = (const float*)d_in[10];
    const float* lsig       = (const float*)d_in[11];
    const float* w_ih       = (const float*)d_in[12];
    const float* w_hh       = (const float*)d_in[13];
    const float* b_ih       = (const float*)d_in[14];
    const float* b_hh       = (const float*)d_in[15];
    const float* w1         = (const float*)d_in[16];
    const float* b1         = (const float*)d_in[17];
    const float* w2         = (const float*)d_in[18];
    const float* b2         = (const float*)d_in[19];
    const float* nslots     = (const float*)d_in[20];
    const float* nh         = (const float*)d_in[21];
    float* out = (float*)d_out;

    cudaFuncSetAttribute(k_prep,  cudaFuncAttributeMaxDynamicSharedMemorySize, PREP_SMEM_BYTES);
    cudaFuncSetAttribute(k_attn,  cudaFuncAttributeMaxDynamicSharedMemorySize, ATTN_SMEM_BYTES);
    cudaFuncSetAttribute(k_upd2,  cudaFuncAttributeMaxDynamicSharedMemorySize, UPD2_SMEM_BYTES);

    k_setup<<<BB+1, 256>>>(mu, lsig, nslots, nh, Wq, Wk);
    k_prep<<<(BB*NN)/128, 256, PREP_SMEM_BYTES>>>(inputs, ln_in_g, ln_in_b);
    k_qp0<<<BB, 256>>>(ln_slots_g, ln_slots_b);
    for (int it = 0; it < 3; it++) {
        k_attn<<<BB*TILES_PER_B, TPB, ATTN_SMEM_BYTES>>>();
        k_upd1<<<BB*SS, 192>>>(Wv, w_ih, b_ih);
        k_upd2<<<BB, 256, UPD2_SMEM_BYTES>>>(w_hh, b_hh, w1, b1, w2, b2,
                                             ln_slots_g, ln_slots_b, ln_mlp_g, ln_mlp_b,
                                             out, it == 2);
    }
}